// round 12
// baseline (speedup 1.0000x reference)
#include <cuda_runtime.h>
#include <cuda_bf16.h>
#include <cstdint>

// Problem constants (SheafGluingPoly: B=4, M=50000, D=8, E=1600000, POLY_K=3, LAM=1)
#define B_CONST 4
#define D_CONST 8
#define MAX_MBD 1600000   // B*M*D
#define MAX_E   1600000

#define ETPB 192          // edge-kernel threads per block (6 warps)
#define EWPB 6            // warps per block

// Scratch: ping-pong vertex state in [m][d][b] layout (b fastest; 128B/vertex),
// plus packed (src,dst) pairs.
__device__ float g_bufA[MAX_MBD];
__device__ float g_bufB[MAX_MBD];
__device__ int2  g_pair[MAX_E];

__device__ __forceinline__ float4 shfl4(float4 a, int m, unsigned mask)
{
    float4 r;
    r.x = __shfl_xor_sync(mask, a.x, m);
    r.y = __shfl_xor_sync(mask, a.y, m);
    r.z = __shfl_xor_sync(mask, a.z, m);
    r.w = __shfl_xor_sync(mask, a.w, m);
    return r;
}
__device__ __forceinline__ void add4(float4& a, float4 b)
{
    a.x += b.x; a.y += b.y; a.z += b.z; a.w += b.w;
}
__device__ __forceinline__ void fma4(float4& acc, float s, float4 r)
{
    acc.x = fmaf(s, r.x, acc.x);
    acc.y = fmaf(s, r.y, acc.y);
    acc.z = fmaf(s, r.z, acc.z);
    acc.w = fmaf(s, r.w, acc.w);
}
// z = S*ps - D*pd (componentwise)
__device__ __forceinline__ float4 zmk(float S, float D, float4 ps, float4 pd)
{
    float4 z;
    z.x = fmaf(S, ps.x, -(D * pd.x));
    z.y = fmaf(S, ps.y, -(D * pd.y));
    z.z = fmaf(S, ps.z, -(D * pd.z));
    z.w = fmaf(S, ps.w, -(D * pd.w));
    return z;
}

// Vector float atomic reduction (sm_90+): one instruction, 16B.
__device__ __forceinline__ void red_add_v4(float* p, float4 v)
{
    asm volatile("red.global.add.v4.f32 [%0], {%1, %2, %3, %4};"
                 :: "l"(p), "f"(v.x), "f"(v.y), "f"(v.z), "f"(v.w)
                 : "memory");
}

// Block-swizzled smem byte address: XOR bits 5-7 with the 256B-block id.
__device__ __forceinline__ unsigned sw_addr(unsigned a)
{
    return a ^ (((a >> 8) & 7u) << 5);
}

// ---------------------------------------------------------------------------
// init (fused with pair packing):
//   v(A)[m][d][b] = c0[b][m][d], out = pc[0]*c0, acc(B) = 0, pair[e]=(src,dst)
// ---------------------------------------------------------------------------
__global__ void init_kernel(const float* __restrict__ c0,
                            const int*   __restrict__ src,
                            const int*   __restrict__ dst,
                            const float* __restrict__ pc,
                            float* __restrict__ out,
                            float* __restrict__ v,
                            float* __restrict__ accz,
                            int2*  __restrict__ pair,
                            int M, int E)
{
    int i = blockIdx.x * blockDim.x + threadIdx.x;
    int n = M * 32;
    if (i < n) {
        int m = i >> 5;
        int d = (i >> 2) & 7;
        int b = i & 3;
        int src_idx = (b * M + m) * 8 + d;   // [b][m][d] layout of c0 / out
        float val = c0[src_idx];
        v[i] = val;
        out[src_idx] = pc[0] * val;
        accz[i] = 0.0f;
    }
    if (i < E) {
        pair[i] = make_int2(src[i], dst[i]);
    }
}

// ---------------------------------------------------------------------------
// edge kernel: 4 edges per warp. lane t: g = t>>3 (edge-in-warp), d = t&7.
// Each lane carries all B=4 batches as float4 (v layout [m][d][b]).
//
// R load path: warp's 4 contiguous edges -> 4 coalesced LDG.128 (data floor),
// staged through swizzled smem, read back as ρ-layout columns (16 LDS,
// conflict-free).
//
// Register k holds column d of row rho(k,d) = ((k01 ^ d01) | 4*k2).
// FUSED keep-low butterfly (peak z live ~5 float4; 48 regs):
//   stage2: z0 += shfl(z2,2); z4 += shfl(z6,2)
//   stage4: R0 = z0+shfl(z0,4) = r[d01];  R1 = z4+shfl(z4,4) = r[d01+4]
// Allgather (6 shfl4) + local transpose matvec; one red.v4 per vertex side.
//
// Occupancy shape: 192 threads x 7 blocks/SM = 42 warps/SM at 48 regs
// (65536-reg file used to 98.4%).
// ---------------------------------------------------------------------------
__global__ void __launch_bounds__(ETPB, 7)
edge_kernel(const float* __restrict__ v,
            const int2*  __restrict__ pair,
            const float* __restrict__ Rsrc,
            const float* __restrict__ Rdst,
            float*       __restrict__ acc,
            int E)
{
    __shared__ float smem[EWPB * 512];   // 2KB per warp

    int t = threadIdx.x & 31;
    int g = t >> 3;
    int d = t & 7;
    int warpG = blockIdx.x * EWPB + (threadIdx.x >> 5);
    int e = warpG * 4 + g;

    char* ws = (char*)(smem + (threadIdx.x >> 5) * 512);

    // ---- coalesced R load (4 edges x 512B) + swizzled smem stage ----
    {
        size_t fbase = (size_t)warpG * 256;           // floats: 4 edges * 64
        size_t flimit = (size_t)E * 64;
        const float4* gS = (const float4*)(Rsrc + fbase);
        const float4* gD = (const float4*)(Rdst + fbase);
        unsigned a0 = (unsigned)t * 16;               // byte offset of chunk 0
        unsigned a1 = a0 + 512;                       // byte offset of chunk 1
        if (fbase + (size_t)t * 4 + 4 <= flimit) {
            float4 s0 = __ldg(gS + t);
            float4 d0 = __ldg(gD + t);
            *(float4*)(ws + sw_addr(a0))        = s0;
            *(float4*)(ws + sw_addr(a0 + 1024)) = d0;
        }
        if (fbase + 128 + (size_t)t * 4 + 4 <= flimit) {
            float4 s1 = __ldg(gS + 32 + t);
            float4 d1 = __ldg(gD + 32 + t);
            *(float4*)(ws + sw_addr(a1))        = s1;
            *(float4*)(ws + sw_addr(a1 + 1024)) = d1;
        }
    }
    __syncwarp();

    if (e >= E) return;

    const unsigned mask = 0xFFu << (t & 24);   // this 8-lane group

    int2 pr = __ldg(pair + e);

    float4 ps = *(const float4*)(v + pr.x * 32 + d * 4);
    float4 pd = *(const float4*)(v + pr.y * 32 + d * 4);

    // ---- conflict-free ρ-layout column reads from smem ----
    // Rs[row][d] of edge g at ws byte: g*256 + ((row^g)<<5) + d*4
    // Rd[row][d]                  at: 1024 + g*256 + ((row^g^4)<<5) + d*4
    float S[8], D[8];
    {
        unsigned q = (unsigned)((d & 3) ^ g);
        unsigned AS = (unsigned)(g * 256 + d * 4) + (q << 5);
        unsigned AD = AS + 1024u;
#pragma unroll
        for (int k = 0; k < 8; k++) {
            unsigned xs = ((unsigned)(k & 3) << 5);
            unsigned hiS = (k & 4) ? 128u : 0u;
            unsigned hiD = (k & 4) ? 0u : 128u;   // ^4 flips row bit 2
            S[k] = *(const float*)(ws + ((AS ^ xs) + hiS));
            D[k] = *(const float*)(ws + ((AD ^ xs) + hiD));
        }
    }

    // ---- fused z production + stage-1 exchange (peak z live ~5 float4) ----
    float4 z0, z2, z4, z6;
    {
        float4 a = zmk(S[0], D[0], ps, pd);
        float4 b = zmk(S[1], D[1], ps, pd);
        z0 = a; add4(z0, shfl4(b, 1, mask));
        a = zmk(S[2], D[2], ps, pd);
        b = zmk(S[3], D[3], ps, pd);
        z2 = a; add4(z2, shfl4(b, 1, mask));
        a = zmk(S[4], D[4], ps, pd);
        b = zmk(S[5], D[5], ps, pd);
        z4 = a; add4(z4, shfl4(b, 1, mask));
        a = zmk(S[6], D[6], ps, pd);
        b = zmk(S[7], D[7], ps, pd);
        z6 = a; add4(z6, shfl4(b, 1, mask));
    }
    // stage 2
    add4(z0, shfl4(z2, 2, mask));
    add4(z4, shfl4(z6, 2, mask));
    // stage 4 (self-exchange; rho invariant under d2)
    float4 R0 = z0; add4(R0, shfl4(z0, 4, mask));   // r[d01][:]
    float4 R1 = z4; add4(R1, shfl4(z4, 4, mask));   // r[d01+4][:]

    // ---- allgather + transpose matvec (local FMAs) ----
    float4 cs = make_float4(0.f, 0.f, 0.f, 0.f);
    float4 cd = make_float4(0.f, 0.f, 0.f, 0.f);
    fma4(cs, S[0], R0);  fma4(cs, S[4], R1);
    fma4(cd, D[0], R0);  fma4(cd, D[4], R1);
#pragma unroll
    for (int x = 1; x < 4; x++) {
        float4 r0x = shfl4(R0, x, mask);   // r[x^d01][:]
        float4 r1x = shfl4(R1, x, mask);   // r[(x^d01)+4][:]
        fma4(cs, S[x],     r0x);
        fma4(cd, D[x],     r0x);
        fma4(cs, S[x + 4], r1x);
        fma4(cd, D[x + 4], r1x);
    }

    red_add_v4(acc + pr.x * 32 + d * 4, cs);
    red_add_v4(acc + pr.y * 32 + d * 4,
               make_float4(-cd.x, -cd.y, -cd.z, -cd.w));
}

// ---------------------------------------------------------------------------
// update: out[b][m][d] += pc[k] * acc[m][d][b]; optionally zero other buffer
// ---------------------------------------------------------------------------
__global__ void update_kernel(const float* __restrict__ acc,
                              const float* __restrict__ pc,
                              int k,
                              float* __restrict__ out,
                              float* __restrict__ zother,
                              int M)
{
    int i = blockIdx.x * blockDim.x + threadIdx.x;
    int n = M * 32;
    if (i >= n) return;
    int m = i >> 5;
    int d = (i >> 2) & 7;
    int b = i & 3;
    float val = acc[i];
    int oi = (b * M + m) * 8 + d;
    out[oi] += pc[k] * val;
    if (zother) zother[i] = 0.0f;
}

// ---------------------------------------------------------------------------
// launch  (7 launches total; ncu -s 5 captures launch #6 = 3rd edge_kernel)
// ---------------------------------------------------------------------------
extern "C" void kernel_launch(void* const* d_in, const int* in_sizes, int n_in,
                              void* d_out, int out_size)
{
    const float* c0  = (const float*)d_in[0];
    const int*   src = (const int*)  d_in[1];
    const int*   dst = (const int*)  d_in[2];
    const float* Rs  = (const float*)d_in[3];
    const float* Rd  = (const float*)d_in[4];
    const float* pc  = (const float*)d_in[5];
    float* out = (float*)d_out;

    int E = in_sizes[1];
    int M = in_sizes[0] / (B_CONST * D_CONST);

    float* bufA;  float* bufB;  int2* pairp;
    cudaGetSymbolAddress((void**)&bufA,  g_bufA);
    cudaGetSymbolAddress((void**)&bufB,  g_bufB);
    cudaGetSymbolAddress((void**)&pairp, g_pair);

    int nV = M * 32;
    int tb = 256;
    int nInit = (nV > E) ? nV : E;
    int gI = (nInit + tb - 1) / tb;
    int gV = (nV + tb - 1) / tb;
    // 4 edges per warp, 6 warps per block = 24 edges per block
    int gE = (E + (EWPB * 4) - 1) / (EWPB * 4);

    init_kernel<<<gI, tb>>>(c0, src, dst, pc, out, bufA, bufB, pairp, M, E);

    // k = 1: B <- L(A); out += pc[1]*B; zero A
    edge_kernel<<<gE, ETPB>>>(bufA, pairp, Rs, Rd, bufB, E);
    update_kernel<<<gV, tb>>>(bufB, pc, 1, out, bufA, M);

    // k = 2: A <- L(B); out += pc[2]*A; zero B
    edge_kernel<<<gE, ETPB>>>(bufB, pairp, Rs, Rd, bufA, E);
    update_kernel<<<gV, tb>>>(bufA, pc, 2, out, bufB, M);

    // k = 3: B <- L(A); out += pc[3]*B
    edge_kernel<<<gE, ETPB>>>(bufA, pairp, Rs, Rd, bufB, E);
    update_kernel<<<gV, tb>>>(bufB, pc, 3, out, nullptr, M);
}

// round 13
// speedup vs baseline: 1.0985x; 1.0985x over previous
#include <cuda_runtime.h>
#include <cuda_bf16.h>
#include <cstdint>

// Problem constants (SheafGluingPoly: B=4, M=50000, D=8, E=1600000, POLY_K=3, LAM=1)
#define B_CONST 4
#define D_CONST 8
#define MAX_MBD 1600000   // B*M*D
#define MAX_E   1600000

#define ETPB 256          // edge kernel: 8 warps/block, 8 edges/warp = 64 edges/block

// Scratch: ping-pong vertex state in [m][d][b] layout (b fastest; 128B/vertex),
// plus packed (src,dst) pairs.
__device__ float g_bufA[MAX_MBD];
__device__ float g_bufB[MAX_MBD];
__device__ int2  g_pair[MAX_E];

__device__ __forceinline__ float4 shfl4(float4 a, int m, unsigned mask)
{
    float4 r;
    r.x = __shfl_xor_sync(mask, a.x, m);
    r.y = __shfl_xor_sync(mask, a.y, m);
    r.z = __shfl_xor_sync(mask, a.z, m);
    r.w = __shfl_xor_sync(mask, a.w, m);
    return r;
}
__device__ __forceinline__ void add4(float4& a, float4 b)
{
    a.x += b.x; a.y += b.y; a.z += b.z; a.w += b.w;
}
__device__ __forceinline__ void fma4(float4& acc, float s, float4 r)
{
    acc.x = fmaf(s, r.x, acc.x);
    acc.y = fmaf(s, r.y, acc.y);
    acc.z = fmaf(s, r.z, acc.z);
    acc.w = fmaf(s, r.w, acc.w);
}
__device__ __forceinline__ float4 mul4(float s, float4 r)
{
    return make_float4(s * r.x, s * r.y, s * r.z, s * r.w);
}

// forward partial over this lane's two dims:
// z = S.x*psl + S.y*psh - (D.x*pdl + D.y*pdh)   (componentwise over b)
__device__ __forceinline__ float4 zfwd(float2 S, float2 Dd,
                                       float4 psl, float4 psh,
                                       float4 pdl, float4 pdh)
{
    float4 z;
    z.x = fmaf(S.x, psl.x, fmaf(S.y, psh.x, -fmaf(Dd.x, pdl.x, Dd.y * pdh.x)));
    z.y = fmaf(S.x, psl.y, fmaf(S.y, psh.y, -fmaf(Dd.x, pdl.y, Dd.y * pdh.y)));
    z.z = fmaf(S.x, psl.z, fmaf(S.y, psh.z, -fmaf(Dd.x, pdl.z, Dd.y * pdh.z)));
    z.w = fmaf(S.x, psl.w, fmaf(S.y, psh.w, -fmaf(Dd.x, pdl.w, Dd.y * pdh.w)));
    return z;
}

// Vector float atomic reduction (sm_90+): one instruction, 16B.
__device__ __forceinline__ void red_add_v4(float* p, float4 v)
{
    asm volatile("red.global.add.v4.f32 [%0], {%1, %2, %3, %4};"
                 :: "l"(p), "f"(v.x), "f"(v.y), "f"(v.z), "f"(v.w)
                 : "memory");
}

// Blackwell 256-bit load (sm_100+): 8 floats, 32B-aligned.
__device__ __forceinline__ void ldg256(const float* p, float4& a, float4& b)
{
    asm volatile("ld.global.nc.v8.f32 {%0,%1,%2,%3,%4,%5,%6,%7}, [%8];"
                 : "=f"(a.x), "=f"(a.y), "=f"(a.z), "=f"(a.w),
                   "=f"(b.x), "=f"(b.y), "=f"(b.z), "=f"(b.w)
                 : "l"(p));
}

// ---------------------------------------------------------------------------
// init (fused with pair packing):
//   v(A)[m][d][b] = c0[b][m][d], out = pc[0]*c0, acc(B) = 0, pair[e]=(src,dst)
// ---------------------------------------------------------------------------
__global__ void init_kernel(const float* __restrict__ c0,
                            const int*   __restrict__ src,
                            const int*   __restrict__ dst,
                            const float* __restrict__ pc,
                            float* __restrict__ out,
                            float* __restrict__ v,
                            float* __restrict__ accz,
                            int2*  __restrict__ pair,
                            int M, int E)
{
    int i = blockIdx.x * blockDim.x + threadIdx.x;
    int n = M * 32;
    if (i < n) {
        int m = i >> 5;
        int d = (i >> 2) & 7;
        int b = i & 3;
        int src_idx = (b * M + m) * 8 + d;   // [b][m][d] layout of c0 / out
        float val = c0[src_idx];
        v[i] = val;
        out[src_idx] = pc[0] * val;
        accz[i] = 0.0f;
    }
    if (i < E) {
        pair[i] = make_int2(src[i], dst[i]);
    }
}

// ---------------------------------------------------------------------------
// edge kernel: 8 edges per warp. lane t: g = t>>2 (edge), c = t&3.
// Lane owns dims {2c, 2c+1} x all 4 batches (v layout [m][d][b]).
//
// R stage: warp's 8 contiguous edges = 4KB, 8 coalesced LDG.128 -> swizzled
// smem (XOR (g&3)<<5) -> 16 conflict-free LDS.64 giving
//   S2[k] = (Rs[a][2c], Rs[a][2c+1]) with a = sigma(k,c) = ((k&3)^c)|(k&4).
//
// 4-lane reduction group (mask 0xF << (t&28)):
//   reduce-scatter (6 shfl4): z[k]+=shfl(z[k^1],1) k even; z[0]+=shfl(z[2],2);
//     z[4]+=shfl(z[6],2) -> z0 = r[c][:], z4 = r[c+4][:]
//   allgather (6 shfl4): r[sigma(x,c)] = shfl(z0,x), r[sigma(x+4,c)] = shfl(z4,x)
// transpose matvec local into 4 accumulators (dims 2c,2c+1 for cs and cd);
// scatter with 4 red.v4 per lane (predicated on e<E).
// ---------------------------------------------------------------------------
__global__ void __launch_bounds__(ETPB, 4)
edge_kernel(const float* __restrict__ v,
            const int2*  __restrict__ pair,
            const float* __restrict__ Rsrc,
            const float* __restrict__ Rdst,
            float*       __restrict__ acc,
            int E)
{
    __shared__ float smem[8 * 1024];   // 4KB per warp (Rs 2KB + Rd 2KB), 8 warps

    int t = threadIdx.x & 31;
    int wid = threadIdx.x >> 5;
    int g = t >> 2;
    int c = t & 3;
    int e0 = (blockIdx.x * 8 + wid) * 8;   // first edge of this warp
    int e = e0 + g;

    char* ws = (char*)(smem + wid * 1024);

    // ---- R stage: 8 LDG.128 coalesced + 8 STS.128 swizzled ----
    {
        size_t fbase = (size_t)e0 * 64;    // floats
        size_t flim  = (size_t)E * 64;
        const float4* gS = (const float4*)(Rsrc + fbase);
        const float4* gD = (const float4*)(Rdst + fbase);
#pragma unroll
        for (int j = 0; j < 4; j++) {
            int gidx = j * 32 + t;                      // float4 granule 0..127
            unsigned gp = (unsigned)gidx >> 4;          // edge-in-warp
            unsigned o  = ((unsigned)gidx & 15u) << 4;  // byte offset in edge
            unsigned ad = gp * 256u + (o ^ ((gp & 3u) << 5));
            if (fbase + (size_t)gidx * 4 + 4 <= flim) {
                float4 s  = __ldg(gS + gidx);
                float4 dd = __ldg(gD + gidx);
                *(float4*)(ws + ad)        = s;
                *(float4*)(ws + 2048 + ad) = dd;
            }
        }
    }
    __syncwarp();

    bool act = (e < E);
    int eC = act ? e : (E > 0 ? E - 1 : 0);
    int2 pr = __ldg(pair + eC);

    // ---- vertex loads: 256-bit each (dims 2c,2c+1 x 4 batches = 32B) ----
    float4 psl, psh, pdl, pdh;
    ldg256(v + pr.x * 32 + c * 8, psl, psh);
    ldg256(v + pr.y * 32 + c * 8, pdl, pdh);

    // ---- LDS.64 column-pair reads (conflict-free with swizzle) ----
    float2 S2[8], D2[8];
    {
        unsigned swz = ((unsigned)g & 3u) << 5;
        unsigned gb  = (unsigned)g * 256u + 0u;
#pragma unroll
        for (int k = 0; k < 8; k++) {
            unsigned a = (((unsigned)k & 3u) ^ (unsigned)c) | ((unsigned)k & 4u);
            unsigned o = a * 32u + (unsigned)c * 8u;
            unsigned ad = gb + (o ^ swz);
            S2[k] = *(const float2*)(ws + ad);
            D2[k] = *(const float2*)(ws + 2048 + ad);
        }
    }

    const unsigned qm = 0xFu << (t & 28);   // 4-lane reduction group

    // ---- fused forward + reduce-scatter (6 shfl4) ----
    float4 z0, z4;
    {
        z0 = zfwd(S2[0], D2[0], psl, psh, pdl, pdh);
        float4 z1 = zfwd(S2[1], D2[1], psl, psh, pdl, pdh);
        add4(z0, shfl4(z1, 1, qm));
        float4 z2 = zfwd(S2[2], D2[2], psl, psh, pdl, pdh);
        float4 z3 = zfwd(S2[3], D2[3], psl, psh, pdl, pdh);
        add4(z2, shfl4(z3, 1, qm));
        add4(z0, shfl4(z2, 2, qm));      // z0 = r[c][:]
        z4 = zfwd(S2[4], D2[4], psl, psh, pdl, pdh);
        float4 z5 = zfwd(S2[5], D2[5], psl, psh, pdl, pdh);
        add4(z4, shfl4(z5, 1, qm));
        float4 z6 = zfwd(S2[6], D2[6], psl, psh, pdl, pdh);
        float4 z7 = zfwd(S2[7], D2[7], psl, psh, pdl, pdh);
        add4(z6, shfl4(z7, 1, qm));
        add4(z4, shfl4(z6, 2, qm));      // z4 = r[c+4][:]
    }

    // ---- allgather (6 shfl4) + local transpose matvec ----
    // S2[k] pairs with r[sigma(k,c)]: k=0 -> z0, k=4 -> z4,
    // k=x -> shfl(z0,x), k=x+4 -> shfl(z4,x)  (x=1..3)
    float4 csl = mul4(S2[0].x, z0), csh = mul4(S2[0].y, z0);
    float4 cdl = mul4(D2[0].x, z0), cdh = mul4(D2[0].y, z0);
    fma4(csl, S2[4].x, z4);  fma4(csh, S2[4].y, z4);
    fma4(cdl, D2[4].x, z4);  fma4(cdh, D2[4].y, z4);
#pragma unroll
    for (int x = 1; x < 4; x++) {
        float4 r0 = shfl4(z0, x, qm);    // r[x^c][:]
        float4 r1 = shfl4(z4, x, qm);    // r[(x^c)+4][:]
        fma4(csl, S2[x].x, r0);      fma4(csh, S2[x].y, r0);
        fma4(cdl, D2[x].x, r0);      fma4(cdh, D2[x].y, r0);
        fma4(csl, S2[x + 4].x, r1);  fma4(csh, S2[x + 4].y, r1);
        fma4(cdl, D2[x + 4].x, r1);  fma4(cdh, D2[x + 4].y, r1);
    }

    if (act) {
        float* as = acc + pr.x * 32 + c * 8;
        red_add_v4(as,     csl);
        red_add_v4(as + 4, csh);
        float* ad = acc + pr.y * 32 + c * 8;
        red_add_v4(ad,     make_float4(-cdl.x, -cdl.y, -cdl.z, -cdl.w));
        red_add_v4(ad + 4, make_float4(-cdh.x, -cdh.y, -cdh.z, -cdh.w));
    }
}

// ---------------------------------------------------------------------------
// update: out[b][m][d] += pc[k] * acc[m][d][b]; optionally zero other buffer
// ---------------------------------------------------------------------------
__global__ void update_kernel(const float* __restrict__ acc,
                              const float* __restrict__ pc,
                              int k,
                              float* __restrict__ out,
                              float* __restrict__ zother,
                              int M)
{
    int i = blockIdx.x * blockDim.x + threadIdx.x;
    int n = M * 32;
    if (i >= n) return;
    int m = i >> 5;
    int d = (i >> 2) & 7;
    int b = i & 3;
    float val = acc[i];
    int oi = (b * M + m) * 8 + d;
    out[oi] += pc[k] * val;
    if (zother) zother[i] = 0.0f;
}

// ---------------------------------------------------------------------------
// launch  (7 launches total; ncu -s 5 captures launch #6 = 3rd edge_kernel)
// ---------------------------------------------------------------------------
extern "C" void kernel_launch(void* const* d_in, const int* in_sizes, int n_in,
                              void* d_out, int out_size)
{
    const float* c0  = (const float*)d_in[0];
    const int*   src = (const int*)  d_in[1];
    const int*   dst = (const int*)  d_in[2];
    const float* Rs  = (const float*)d_in[3];
    const float* Rd  = (const float*)d_in[4];
    const float* pc  = (const float*)d_in[5];
    float* out = (float*)d_out;

    int E = in_sizes[1];
    int M = in_sizes[0] / (B_CONST * D_CONST);

    float* bufA;  float* bufB;  int2* pairp;
    cudaGetSymbolAddress((void**)&bufA,  g_bufA);
    cudaGetSymbolAddress((void**)&bufB,  g_bufB);
    cudaGetSymbolAddress((void**)&pairp, g_pair);

    int nV = M * 32;
    int tb = 256;
    int nInit = (nV > E) ? nV : E;
    int gI = (nInit + tb - 1) / tb;
    int gV = (nV + tb - 1) / tb;
    // 8 edges per warp, 8 warps per block = 64 edges per block
    int gE = (E + 63) / 64;

    init_kernel<<<gI, tb>>>(c0, src, dst, pc, out, bufA, bufB, pairp, M, E);

    // k = 1: B <- L(A); out += pc[1]*B; zero A
    edge_kernel<<<gE, ETPB>>>(bufA, pairp, Rs, Rd, bufB, E);
    update_kernel<<<gV, tb>>>(bufB, pc, 1, out, bufA, M);

    // k = 2: A <- L(B); out += pc[2]*A; zero B
    edge_kernel<<<gE, ETPB>>>(bufB, pairp, Rs, Rd, bufA, E);
    update_kernel<<<gV, tb>>>(bufA, pc, 2, out, bufB, M);

    // k = 3: B <- L(A); out += pc[3]*B
    edge_kernel<<<gE, ETPB>>>(bufA, pairp, Rs, Rd, bufB, E);
    update_kernel<<<gV, tb>>>(bufB, pc, 3, out, nullptr, M);
}